// round 10
// baseline (speedup 1.0000x reference)
#include <cuda_runtime.h>
#include <cuda_bf16.h>
#include <cuda_fp16.h>
#include <cstdint>

// ---------------------------------------------------------------------------
// Problem constants
// ---------------------------------------------------------------------------
#define BN   8
#define SEQ  2048
#define DIN  1024
#define DM   1024
#define NTOK (BN*SEQ)          // 16384

// ---------------------------------------------------------------------------
// Blocked fp16 operand layout (round-9 validated):
//   operand[row, k] stored as 32KB blocks indexed [row/256][k/64].
//   Block: 256 rows x 128B; row = 64 fp16 k-values, SW128-swizzled.
//   GEMM chunk (K=64) load = TWO contiguous 32KB cp.async.bulk copies.
// Round-10: cluster of 8 CTAs = 2 m-tiles x 4 n-tiles; A blocks multicast to
//   the 4 CTAs sharing the m-tile, B blocks to the 2 sharing the n-tile.
// ---------------------------------------------------------------------------
#define SWZ128(off) ((off) ^ (((off) >> 3) & 0x70))

__device__ uint8_t g_Xq[(size_t)NTOK*DIN*2];
__device__ uint8_t g_Xk[(size_t)NTOK*DIN*2];
__device__ uint8_t g_Xv[(size_t)NTOK*DIN*2];
__device__ uint8_t g_Wq[(size_t)DM*DIN*2];
__device__ uint8_t g_Wk[(size_t)DM*DIN*2];
__device__ uint8_t g_Wv[(size_t)DM*DIN*2];
__device__ uint8_t g_Qb[(size_t)NTOK*DM*2];          // 4MB/batch, nkc=16
__device__ uint8_t g_Kb[(size_t)NTOK*DM*2];
__device__ uint8_t g_Vt[(size_t)BN*DM*SEQ*2];        // rows=v, k=s, nkc=32, 4MB/batch
__device__ uint8_t g_Pb[(size_t)BN*SEQ*SEQ*2];       // rows=q, k=s, nkc=32, 8MB/batch
__device__ float   g_rs[(size_t)BN*SEQ];

// ---------------------------------------------------------------------------
// Helpers available on base compute_103
// ---------------------------------------------------------------------------
__device__ __forceinline__ uint32_t smem_u32(const void* p) {
    uint32_t a;
    asm("{ .reg .u64 t; cvta.to.shared.u64 t, %1; cvt.u32.u64 %0, t; }"
        : "=r"(a) : "l"(p));
    return a;
}
__device__ __forceinline__ uint32_t cluster_rank() {
    uint32_t r;
    asm("mov.u32 %0, %%cluster_ctarank;" : "=r"(r));
    return r;
}
#define CLUSTER_SYNC() do { \
    asm volatile("barrier.cluster.arrive.aligned;" ::: "memory"); \
    asm volatile("barrier.cluster.wait.aligned;"   ::: "memory"); \
} while (0)

__device__ __forceinline__ void cp16(uint32_t dst, const void* src) {
    asm volatile("cp.async.cg.shared.global [%0], [%1], 16;" :: "r"(dst), "l"(src));
}
#define CP_COMMIT()  asm volatile("cp.async.commit_group;" ::: "memory")
#define CP_WAIT(N)   asm volatile("cp.async.wait_group %0;" :: "n"(N) : "memory")

__device__ __forceinline__ void mma16816h(float* c, const uint32_t* a,
                                          uint32_t b0, uint32_t b1) {
    asm volatile(
        "mma.sync.aligned.m16n8k16.row.col.f32.f16.f16.f32 "
        "{%0,%1,%2,%3}, {%4,%5,%6,%7}, {%8,%9}, {%0,%1,%2,%3};"
        : "+f"(c[0]), "+f"(c[1]), "+f"(c[2]), "+f"(c[3])
        : "r"(a[0]), "r"(a[1]), "r"(a[2]), "r"(a[3]), "r"(b0), "r"(b1));
}

__device__ __forceinline__ uint32_t pkh2(__half a, __half b) {
    __half2 t; t.x = a; t.y = b;
    return *(uint32_t*)&t;
}
__device__ __forceinline__ void store_blk1(uint8_t* base, int row, int k,
                                           int nkc, float v) {
    const size_t blk = (((size_t)(row >> 8)) * nkc + (k >> 6)) << 15;
    const uint32_t off = (uint32_t)(row & 255) * 128 + (k & 63) * 2;
    *(__half*)(base + blk + SWZ128(off)) = __float2half(v);
}

// bulk copies: contiguous gmem -> smem, completion via mbarrier tx-bytes
__device__ __forceinline__ void bulk_mc(uint32_t dst, const void* src,
                                        uint32_t bytes, uint32_t mbar,
                                        uint16_t mask) {
    asm volatile(
        "cp.async.bulk.shared::cluster.global.mbarrier::complete_tx::bytes"
        ".multicast::cluster [%0], [%1], %2, [%3], %4;"
        :: "r"(dst), "l"(src), "r"(bytes), "r"(mbar), "h"(mask) : "memory");
}
#define MBAR_INIT(addr, cnt) \
    asm volatile("mbarrier.init.shared.b64 [%0], %1;" :: "r"((uint32_t)(addr)), "r"((uint32_t)(cnt)) : "memory")
#define MBAR_EXPECT(addr, tx) \
    asm volatile("mbarrier.arrive.expect_tx.shared.b64 _, [%0], %1;" :: "r"((uint32_t)(addr)), "r"((uint32_t)(tx)) : "memory")
#define MBAR_WAIT(mbar, par) do { \
    uint32_t _m = (uint32_t)(mbar), _p = (uint32_t)(par), _d; \
    asm volatile("{\n\t.reg .pred p;\n\t" \
        "mbarrier.try_wait.parity.acquire.cta.shared::cta.b64 p, [%1], %2;\n\t" \
        "selp.b32 %0, 1, 0, p;\n\t}" : "=r"(_d) : "r"(_m), "r"(_p) : "memory"); \
    if (!_d) { \
        asm volatile("{\n\t.reg .pred P1;\n\t" \
            "WL_%=:\n\t" \
            "mbarrier.try_wait.parity.acquire.cta.shared::cta.b64 P1, [%0], %1, 0x989680;\n\t" \
            "@P1 bra.uni WD_%=;\n\tbra.uni WL_%=;\n\tWD_%=:\n\t}" \
            :: "r"(_m), "r"(_p) : "memory"); \
    } \
} while (0)

// ---------------------------------------------------------------------------
// tcgen05 helpers — ONLY compiled when the build has a compute_103a pass.
// ---------------------------------------------------------------------------
#if defined(__CUDA_ARCH_FEAT_SM103_ALL)
__device__ __forceinline__ uint32_t elect_one_pred() {
    uint32_t pred;
    asm volatile(
        "{\n\t.reg .pred p;\n\t"
        "elect.sync _|p, 0xFFFFFFFF;\n\t"
        "selp.b32 %0, 1, 0, p;\n\t}"
        : "=r"(pred));
    return pred;
}
#define TCGEN05_ALLOC(a, n) \
    asm volatile("tcgen05.alloc.cta_group::1.sync.aligned.shared::cta.b32 [%0], %1;" \
        :: "r"((uint32_t)(a)), "r"((uint32_t)(n)) : "memory")
#define TCGEN05_RELINQUISH() \
    asm volatile("tcgen05.relinquish_alloc_permit.cta_group::1.sync.aligned;")
#define TCGEN05_DEALLOC(t, n) \
    asm volatile("tcgen05.dealloc.cta_group::1.sync.aligned.b32 %0, %1;" :: "r"(t), "r"((uint32_t)(n)))
#define TCGEN05_COMMIT_MC(m, mask) \
    asm volatile("tcgen05.commit.cta_group::1.mbarrier::arrive::one.shared::cluster.multicast::cluster.b64 [%0], %1;" \
        :: "r"((uint32_t)(m)), "h"((uint16_t)(mask)) : "memory")
#define TCGEN05_WAIT_LD()    asm volatile("tcgen05.wait::ld.sync.aligned;" ::: "memory")
#define TCGEN05_FENCE_AFTER() asm volatile("tcgen05.fence::after_thread_sync;" ::: "memory")
#define TCGEN05_LD_32X32B_X32(r, ta) \
    asm volatile( \
        "tcgen05.ld.sync.aligned.32x32b.x32.b32 " \
        "{%0, %1, %2, %3, %4, %5, %6, %7, " \
        " %8, %9, %10, %11, %12, %13, %14, %15, " \
        " %16, %17, %18, %19, %20, %21, %22, %23, " \
        " %24, %25, %26, %27, %28, %29, %30, %31}, [%32];" \
        : "=r"((r)[0]),  "=r"((r)[1]),  "=r"((r)[2]),  "=r"((r)[3]), \
          "=r"((r)[4]),  "=r"((r)[5]),  "=r"((r)[6]),  "=r"((r)[7]), \
          "=r"((r)[8]),  "=r"((r)[9]),  "=r"((r)[10]), "=r"((r)[11]), \
          "=r"((r)[12]), "=r"((r)[13]), "=r"((r)[14]), "=r"((r)[15]), \
          "=r"((r)[16]), "=r"((r)[17]), "=r"((r)[18]), "=r"((r)[19]), \
          "=r"((r)[20]), "=r"((r)[21]), "=r"((r)[22]), "=r"((r)[23]), \
          "=r"((r)[24]), "=r"((r)[25]), "=r"((r)[26]), "=r"((r)[27]), \
          "=r"((r)[28]), "=r"((r)[29]), "=r"((r)[30]), "=r"((r)[31]) \
        : "r"(ta))
static constexpr uint64_t SMEM_DESC_BASE_SW128 =
    (uint64_t(2)  << 61) | (uint64_t(1) << 46) | (uint64_t(64) << 32) | (uint64_t(1) << 16);
#define MAKE_SMEM_DESC(ba) (SMEM_DESC_BASE_SW128 | ((uint64_t)((ba) >> 4) & 0x3FFF))
__device__ __forceinline__ void mma_f16_ss(uint32_t d, uint64_t ad, uint64_t bd,
                                           uint32_t idesc, bool acc) {
    uint32_t en = acc ? 1u : 0u;
    asm volatile(
        "{\n\t.reg .pred p;\n\t"
        "setp.ne.u32 p, %5, 0;\n\t"
        "tcgen05.mma.cta_group::1.kind::f16 [%0], %1, %2, %3, {%4, %4, %4, %4}, p;\n\t"
        "}"
        :: "r"(d), "l"(ad), "l"(bd), "r"(idesc), "r"(0u), "r"(en)
        : "memory");
}
#endif  // __CUDA_ARCH_FEAT_SM103_ALL

// ---------------------------------------------------------------------------
// GEMM: C[M,N] = A[M,K] * B[N,K]^T, fp16 operands (blocked), cluster-8 CTAs:
//   rank r: rm=r>>2 (m-tile within pair), rn=r&3 (n-tile within quad).
//   A-producers ranks {0,4} multicast 32KB A blocks to their m-group (mask 4);
//   B-producers ranks {0..3} multicast B to their n-group (mask 2).
//   Per CTA: cg1 256x256 MMA exactly as round 9 (two M=128 TMEM accums).
//   full[st]: tx 64KB. done[st]: tcgen05 commit MULTICAST to {self, prodA,
//   prodB} — producers reload a stage only after all its readers finished.
//   Receivers re-arm expect_tx BEFORE committing (no expect/load race).
// MODE 0: dual projection (z selects QK operand set), bias[n], nkc=16
// MODE 2: Vt = Wv * Xv^T (+bias[m]); nkc=32
// MODE 3: e=expf(acc*alpha) f16 out + row-sum atomics, nkc=32
// MODE 4: f32 out = acc / rowsum[m]
// ---------------------------------------------------------------------------
constexpr int OFF_B  = 32768;
constexpr int STAGE  = 65536;                     // 32KB A + 32KB B
constexpr int SMEM_DATA = 1024;
constexpr int SMEM_TOTAL = SMEM_DATA + 3 * STAGE; // 197632

template <int MODE>
__global__ void __launch_bounds__(256, 1) __cluster_dims__(8, 1, 1) tc_gemm(
    const uint8_t* __restrict__ Ab, const uint8_t* __restrict__ Bb,
    const uint8_t* __restrict__ A2b, const uint8_t* __restrict__ B2b,
    const float* __restrict__ bias, const float* __restrict__ bias2,
    float* __restrict__ Cf, uint8_t* __restrict__ Cb, uint8_t* __restrict__ C2b,
    float* __restrict__ rs,
    int K, float alpha,
    size_t sAb, size_t sBb, size_t sC)
{
    extern __shared__ char smem[];
    const int tid   = threadIdx.x;
    const size_t zb = blockIdx.z;
    const uint32_t rank = cluster_rank();
    const int rm = (int)(rank >> 2), rn = (int)(rank & 3);
    const int mTile = blockIdx.y * 2 + rm;
    const int nTile = (blockIdx.x >> 3) * 4 + rn;
    const int m0    = mTile * 256;
    const int n0    = nTile * 256;
    const int NC    = K >> 6;                 // 64-k chunks

    if (MODE == 0 && zb == 1) {
        Ab = A2b; Bb = B2b; Cb = C2b; bias = bias2;
    }
    Ab += zb * sAb;  Bb += zb * sBb;
    const size_t blkA0 = ((size_t)(m0 >> 8)) * NC;
    const size_t blkB0 = ((size_t)(n0 >> 8)) * NC;

#if defined(__CUDA_ARCH_FEAT_SM103_ALL)
    // ======================= tcgen05 path (sm_103a) ========================
    const uint32_t sb = smem_u32(smem);
    const bool isProdA = (rn == 0);                  // ranks 0, 4
    const bool isProdB = (rm == 0);                  // ranks 0..3
    const uint16_t maskA = (uint16_t)(0x0Fu << (rm * 4));
    const uint16_t maskB = (uint16_t)(0x11u << rn);
    // commit notifies: self, my A-producer, my B-producer
    const uint16_t doneMask =
        (uint16_t)((1u << rank) | (1u << (rm * 4)) | (1u << rn));
    // arrivals per chunk-round into done[] at this rank
    const uint32_t doneCnt = (rank == 0) ? 5u : (rank == 4) ? 4u
                           : (rank < 4)  ? 2u : 1u;

    if (tid < 32) TCGEN05_ALLOC(sb + 0, 512);
    if (tid >= 32 && tid < 64) TCGEN05_RELINQUISH();
    if (tid == 0) {
#pragma unroll
        for (int s = 0; s < 3; ++s) {
            MBAR_INIT(sb + 8  + 8 * s, 1);         // full (tx-based)
            MBAR_INIT(sb + 32 + 8 * s, doneCnt);   // mma done (multicast arrivals)
        }
    }
    __syncthreads();
    uint32_t tmem;
    asm volatile("ld.shared.b32 %0, [%1];" : "=r"(tmem) : "r"(sb + 0));

    constexpr uint32_t IDESC =
        (1u << 4) | ((256 / 8) << 17) | ((128 / 16) << 24);

    // pre-arm full[0..2] BEFORE any producer in the cluster can load
    if (tid < 32 && elect_one_pred()) {
#pragma unroll
        for (int s = 0; s < 3; ++s) MBAR_EXPECT(sb + 8 + 8 * s, STAGE);
    }
    CLUSTER_SYNC();   // all expects + barrier inits visible cluster-wide

    if (tid < 32 && elect_one_pred()) {
        auto load_chunk = [&](int kc, int st) {
            const uint32_t base = sb + SMEM_DATA + st * STAGE;
            if (isProdA)
                bulk_mc(base,         Ab + ((blkA0 + kc) << 15), 32768,
                        sb + 8 + 8 * st, maskA);
            if (isProdB)
                bulk_mc(base + OFF_B, Bb + ((blkB0 + kc) << 15), 32768,
                        sb + 8 + 8 * st, maskB);
        };

        load_chunk(0, 0);
        load_chunk(1, 1);
        load_chunk(2, 2);

        int fph[3] = {0, 0, 0}, dph[3] = {0, 0, 0};
        for (int c = 0; c < NC; ++c) {
            const int st = c % 3;
            MBAR_WAIT(sb + 8 + 8 * st, fph[st]);
            fph[st] ^= 1;
            // re-arm this stage for chunk c+3 BEFORE committing (commit gates
            // the producers' reload, so every receiver's expect precedes it)
            if (c + 3 < NC) MBAR_EXPECT(sb + 8 + 8 * st, STAGE);

            const uint32_t base = sb + SMEM_DATA + st * STAGE;
            const uint64_t daA0 = MAKE_SMEM_DESC(base);
            const uint64_t daA1 = MAKE_SMEM_DESC(base + 16384);
            const uint64_t db   = MAKE_SMEM_DESC(base + OFF_B);
#pragma unroll
            for (int half = 0; half < 2; ++half) {
                const uint64_t da = half ? daA1 : daA0;
                const uint32_t dt = tmem + half * 256;
#pragma unroll
                for (int ks = 0; ks < 4; ++ks)
                    mma_f16_ss(dt, da + ks * 2, db + ks * 2, IDESC,
                               !(c == 0 && ks == 0));
            }
            TCGEN05_COMMIT_MC(sb + 32 + 8 * st, doneMask);

            if (c > 0) {
                const int sp = (c - 1) % 3;
                MBAR_WAIT(sb + 32 + 8 * sp, dph[sp]);   // readers done w/ sp
                dph[sp] ^= 1;
                if (c + 2 < NC) load_chunk(c + 2, sp);
            }
        }
        MBAR_WAIT(sb + 32 + 8 * ((NC - 1) % 3), dph[(NC - 1) % 3]);
    }
    __syncthreads();
    TCGEN05_FENCE_AFTER();

    // epilogue: warps 0-3 -> D0 (rows 0-127), warps 4-7 -> D1 (rows 128-255)
    {
        const int half = tid >> 7;
        const int w4   = (tid >> 5) & 3;
        const int lid  = tid & 31;
        const int m    = m0 + half * 128 + w4 * 32 + lid;
        const uint32_t dt = tmem + half * 256;
        float inv = 1.0f, lsum = 0.0f, bm = 0.0f;
        if (MODE == 4) inv = 1.0f / rs[zb * SEQ + m];
        if (MODE == 2) bm  = bias[m];
        for (int j0 = 0; j0 < 256; j0 += 32) {
            uint32_t r[32];
            TCGEN05_LD_32X32B_X32(r, dt + j0);
            TCGEN05_WAIT_LD();
            if (MODE == 4) {
                float4* dst = (float4*)(Cf + zb * sC + (size_t)m * DM + n0 + j0);
#pragma unroll
                for (int i = 0; i < 8; ++i) {
                    float4 v;
                    v.x = __uint_as_float(r[4 * i + 0]) * inv;
                    v.y = __uint_as_float(r[4 * i + 1]) * inv;
                    v.z = __uint_as_float(r[4 * i + 2]) * inv;
                    v.w = __uint_as_float(r[4 * i + 3]) * inv;
                    dst[i] = v;
                }
            } else {   // MODE 0 / 2 / 3: blocked fp16 store (32 vals = 64B)
                uint32_t H[16];
#pragma unroll
                for (int i = 0; i < 32; i += 2) {
                    float v0, v1;
                    if (MODE == 3) {
                        v0 = __expf(__uint_as_float(r[i])     * alpha);
                        v1 = __expf(__uint_as_float(r[i + 1]) * alpha);
                        lsum += v0 + v1;
                    } else if (MODE == 0) {
                        v0 = __uint_as_float(r[i])     + bias[n0 + j0 + i];
                        v1 = __uint_as_float(r[i + 1]) + bias[n0 + j0 + i + 1];
                    } else {
                        v0 = __uint_as_float(r[i])     + bm;
                        v1 = __uint_as_float(r[i + 1]) + bm;
                    }
                    H[i >> 1] = pkh2(__float2half(v0), __float2half(v1));
                }
                uint8_t* base;
                size_t blk;
                const int row = m & 255;
                if (MODE == 0) {          // Q/K: 4MB/batch(by m), nkc = 16
                    base = Cb + (size_t)(m >> 11) * 4194304u;
                    blk  = ((((size_t)((m & 2047) >> 8)) * 16) + ((n0 + j0) >> 6)) << 15;
                } else if (MODE == 3) {   // P: 8MB/batch, nkc = 32
                    base = Cb + zb * 8388608u;
                    blk  = ((((size_t)(m >> 8)) * 32) + ((n0 + j0) >> 6)) << 15;
                } else {                  // Vt: 4MB/batch, nkc = 32
                    base = Cb + zb * 4194304u;
                    blk  = ((((size_t)(m >> 8)) * 32) + ((n0 + j0) >> 6)) << 15;
                }
                const uint32_t u0 = (uint32_t)(((n0 + j0) & 63) >> 3);  // 0 or 4
#pragma unroll
                for (int q = 0; q < 4; ++q) {
                    uint4 hv;
                    hv.x = H[4*q]; hv.y = H[4*q+1]; hv.z = H[4*q+2]; hv.w = H[4*q+3];
                    *(uint4*)(base + blk +
                              SWZ128((uint32_t)row * 128 + (u0 + q) * 16)) = hv;
                }
            }
        }
        if (MODE == 3) atomicAdd(&rs[zb * SEQ + m], lsum);
    }
    __syncthreads();
    if (tid < 32) TCGEN05_DEALLOC(tmem, 512);
    CLUSTER_SYNC();   // no CTA exits while peer multicasts may target its smem

#elif defined(__CUDA_ARCH__)
    // ================= mma.sync fallback (base compute_103) =================
    // Correctness insurance only; no multicast (direct per-CTA loads).
    constexpr int STR = 20;
    constexpr int TILE_W = 128 * STR;
    constexpr int STAGE_W = 2 * TILE_W;
    const uint32_t sbase = smem_u32(smem);
    const int lane = tid & 31, wid = tid >> 5;
    const int wm = wid >> 1, wn = wid & 1;
    const int g = lane >> 2, tg = lane & 3;
    const int NC32 = K >> 5;

    auto load_chunk = [&](int c32, int st, int mbase, int nbase) {
        const int q = tid & 3, r0 = tid >> 2;
        const uint32_t dst0 = sbase + st * STAGE_W * 4;
        const int kc = c32 >> 1, h = c32 & 1;
#pragma unroll
        for (int i = 0; i < 2; ++i) {
            const int ra = mbase + r0 + 64 * i;
            const int rb = nbase + r0 + 64 * i;
            const uint32_t ro = (uint32_t)((r0 + 64 * i) * STR + q * 4) * 4;
            const size_t ba = (((size_t)(ra >> 8)) * NC + kc) << 15;
            const size_t bb = (((size_t)(rb >> 8)) * NC + kc) << 15;
            const uint32_t oa = (uint32_t)(ra & 255) * 128 + h * 64 + q * 16;
            const uint32_t ob = (uint32_t)(rb & 255) * 128 + h * 64 + q * 16;
            cp16(dst0 + ro,                Ab + ba + SWZ128(oa));
            cp16(dst0 + TILE_W * 4 + ro,   Bb + bb + SWZ128(ob));
        }
    };

    for (int mh = 0; mh < 2; ++mh) {
        const int mb0 = m0 + mh * 128;
        for (int np = 0; np < 2; ++np) {
            const int nb0 = n0 + np * 128;

            float acc[2][8][4];
#pragma unroll
            for (int a = 0; a < 2; ++a)
#pragma unroll
                for (int b = 0; b < 8; ++b)
#pragma unroll
                    for (int c = 0; c < 4; ++c) acc[a][b][c] = 0.0f;

            load_chunk(0, 0, mb0, nb0); CP_COMMIT();

            for (int c = 0; c < NC32; ++c) {
                const int st = c & 1;
                if (c + 1 < NC32) { load_chunk(c + 1, st ^ 1, mb0, nb0); CP_COMMIT(); CP_WAIT(1); }
                else              { CP_WAIT(0); }
                __syncthreads();

                const uint32_t* s0 = (const uint32_t*)smem + st * STAGE_W;
#pragma unroll
                for (int ks = 0; ks < 2; ++ks) {
                    uint32_t af[2][4];
#pragma unroll
                    for (int mt = 0; mt < 2; ++mt) {
                        const int rb = wm * 32 + mt * 16;
                        const uint32_t* pa = s0 + (rb + g) * STR + ks * 8 + tg;
                        af[mt][0] = pa[0];           af[mt][2] = pa[4];
                        af[mt][1] = pa[8 * STR];     af[mt][3] = pa[8 * STR + 4];
                    }
#pragma unroll
                    for (int nt = 0; nt < 8; ++nt) {
                        const int nb = wn * 64 + nt * 8;
                        const uint32_t* pb = s0 + TILE_W + (nb + g) * STR + ks * 8 + tg;
                        const uint32_t b0 = pb[0], b1 = pb[4];
#pragma unroll
                        for (int mt = 0; mt < 2; ++mt)
                            mma16816h(acc[mt][nt], af[mt], b0, b1);
                    }
                }
                __syncthreads();
            }

#pragma unroll
            for (int mt = 0; mt < 2; ++mt) {
#pragma unroll
                for (int nt = 0; nt < 8; ++nt) {
                    const int m1 = mb0 + wm * 32 + mt * 16 + g;
                    const int m2 = m1 + 8;
                    const int n  = nb0 + wn * 64 + nt * 8 + tg * 2;
                    const float* a = acc[mt][nt];
                    if (MODE == 4) {
                        const float i1 = 1.0f / rs[zb * SEQ + m1];
                        const float i2 = 1.0f / rs[zb * SEQ + m2];
                        float2 v0; v0.x = a[0] * i1; v0.y = a[1] * i1;
                        float2 v1; v1.x = a[2] * i2; v1.y = a[3] * i2;
                        *(float2*)(Cf + zb * sC + (size_t)m1 * DM + n) = v0;
                        *(float2*)(Cf + zb * sC + (size_t)m2 * DM + n) = v1;
                    } else if (MODE == 0) {
#pragma unroll
                        for (int e = 0; e < 4; ++e) {
                            const int m = (e < 2) ? m1 : m2;
                            const int nn = n + (e & 1);
                            store_blk1(Cb + (size_t)(m >> 11) * 4194304u,
                                       m & 2047, nn, 16, a[e] + bias[nn]);
                        }
                    } else if (MODE == 3) {
                        float e0 = __expf(a[0] * alpha), e1 = __expf(a[1] * alpha);
                        float e2 = __expf(a[2] * alpha), e3 = __expf(a[3] * alpha);
                        atomicAdd(&rs[zb * SEQ + m1], e0 + e1);
                        atomicAdd(&rs[zb * SEQ + m2], e2 + e3);
                        uint8_t* base = Cb + zb * 8388608u;
                        store_blk1(base, m1, n,     32, e0);
                        store_blk1(base, m1, n + 1, 32, e1);
                        store_blk1(base, m2, n,     32, e2);
                        store_blk1(base, m2, n + 1, 32, e3);
                    } else {  // MODE 2
                        uint8_t* base = Cb + zb * 4194304u;
#pragma unroll
                        for (int e = 0; e < 4; ++e) {
                            const int m = (e < 2) ? m1 : m2;
                            const int nn = n + (e & 1);
                            store_blk1(base, m, nn, 32, a[e] + bias[m]);
                        }
                    }
                }
            }
            __syncthreads();
        }
    }
#endif
}

// ---------------------------------------------------------------------------
// f32 -> blocked fp16 (K fixed = 1024; nkc = 16). z selects among 3 tensors.
// ---------------------------------------------------------------------------
__global__ void __launch_bounds__(256) split3_k(
    const float* __restrict__ x0, const float* __restrict__ x1,
    const float* __restrict__ x2,
    uint8_t* __restrict__ d0, uint8_t* __restrict__ d1,
    uint8_t* __restrict__ d2, int nunits)
{
    const int z = blockIdx.z;
    const float* x = (z == 0) ? x0 : (z == 1) ? x1 : x2;
    uint8_t*   dst = (z == 0) ? d0 : (z == 1) ? d1 : d2;
    for (int u = blockIdx.x * 256 + threadIdx.x; u < nunits; u += gridDim.x * 256) {
        const int r = u >> 7;
        const int j = u & 127;
        const float4 f0 = *(const float4*)(x + ((size_t)r << 10) + (j << 3));
        const float4 f1 = *(const float4*)(x + ((size_t)r << 10) + (j << 3) + 4);
        uint4 hv;
        hv.x = pkh2(__float2half(f0.x), __float2half(f0.y));
        hv.y = pkh2(__float2half(f0.z), __float2half(f0.w));
        hv.z = pkh2(__float2half(f1.x), __float2half(f1.y));
        hv.w = pkh2(__float2half(f1.z), __float2half(f1.w));
        const size_t blk = ((((size_t)(r >> 8)) << 4) + (j >> 3)) << 15;  // nkc=16
        const uint32_t ro = (uint32_t)(r & 255) * 128 + (j & 7) * 16;
        *(uint4*)(dst + blk + SWZ128(ro)) = hv;
    }
}

__global__ void __launch_bounds__(1024) zero_k(float* __restrict__ p, int n)
{
    int i = blockIdx.x * 1024 + threadIdx.x;
    if (i < n) p[i] = 0.0f;
}

// ---------------------------------------------------------------------------
extern "C" void kernel_launch(void* const* d_in, const int* in_sizes, int n_in,
                              void* d_out, int out_size)
{
    (void)in_sizes; (void)n_in; (void)out_size;
    const float* q  = (const float*)d_in[0];
    const float* kx = (const float*)d_in[1];
    const float* vx = (const float*)d_in[2];
    const float* Wq = (const float*)d_in[3];
    const float* bq = (const float*)d_in[4];
    const float* Wk = (const float*)d_in[5];
    const float* bk = (const float*)d_in[6];
    const float* Wv = (const float*)d_in[7];
    const float* bv = (const float*)d_in[8];
    float* out = (float*)d_out;

    uint8_t *Xq, *Xk, *Xv, *Wqb, *Wkb, *Wvb, *Qb, *Kb, *Vt, *Pb;
    float* rs;
    cudaGetSymbolAddress((void**)&Xq,  g_Xq);  cudaGetSymbolAddress((void**)&Xk,  g_Xk);
    cudaGetSymbolAddress((void**)&Xv,  g_Xv);
    cudaGetSymbolAddress((void**)&Wqb, g_Wq);  cudaGetSymbolAddress((void**)&Wkb, g_Wk);
    cudaGetSymbolAddress((void**)&Wvb, g_Wv);
    cudaGetSymbolAddress((void**)&Qb,  g_Qb);  cudaGetSymbolAddress((void**)&Kb,  g_Kb);
    cudaGetSymbolAddress((void**)&Vt,  g_Vt);  cudaGetSymbolAddress((void**)&Pb,  g_Pb);
    cudaGetSymbolAddress((void**)&rs,  g_rs);

    cudaFuncSetAttribute(tc_gemm<0>, cudaFuncAttributeMaxDynamicSharedMemorySize, SMEM_TOTAL);
    cudaFuncSetAttribute(tc_gemm<2>, cudaFuncAttributeMaxDynamicSharedMemorySize, SMEM_TOTAL);
    cudaFuncSetAttribute(tc_gemm<3>, cudaFuncAttributeMaxDynamicSharedMemorySize, SMEM_TOTAL);
    cudaFuncSetAttribute(tc_gemm<4>, cudaFuncAttributeMaxDynamicSharedMemorySize, SMEM_TOTAL);

    // 1. splits (inputs, weights) + zero row sums
    split3_k<<<dim3(2048, 1, 3), 256>>>(q, kx, vx, Xq, Xk, Xv, NTOK * DIN / 8);
    split3_k<<<dim3(512,  1, 3), 256>>>(Wq, Wk, Wv, Wqb, Wkb, Wvb, DM * DIN / 8);
    zero_k<<<(BN * SEQ + 1023) / 1024, 1024>>>(rs, BN * SEQ);

    // 2. Q and K projections in ONE launch (z selects operand set)
    //    cluster 8 along x: 1 n-group (Nt=4), m-pairs = 32
    tc_gemm<0><<<dim3(8, 32, 2), 256, SMEM_TOTAL>>>(
        Xq, Wqb, Xk, Wkb, bq, bk, nullptr, Qb, Kb, nullptr,
        DIN, 1.0f, 0, 0, 0);

    // 3. Vt = Wv * Xv^T (+bv): Nt=8 -> 2 n-groups, Mt=4 -> 2 m-pairs
    tc_gemm<2><<<dim3(16, 2, BN), 256, SMEM_TOTAL>>>(
        Wvb, Xv, nullptr, nullptr, bv, nullptr, nullptr, Vt, nullptr, nullptr,
        DIN, 1.0f, 0, 4194304u, 0);

    // 4. scores + exp + row sums -> fp16 P: Nt=8, Mt=8
    tc_gemm<3><<<dim3(16, 4, BN), 256, SMEM_TOTAL>>>(
        Qb, Kb, nullptr, nullptr, nullptr, nullptr, nullptr, Pb, nullptr, rs,
        DM, 0.03125f, 4194304u, 4194304u, 0);

    // 5. O = (P * Vt^T) / rowsum: Nt=4, Mt=8
    tc_gemm<4><<<dim3(8, 4, BN), 256, SMEM_TOTAL>>>(
        Pb, Vt, nullptr, nullptr, nullptr, nullptr, out, nullptr, nullptr, rs,
        SEQ, 1.0f, 8388608u, 4194304u, (size_t)SEQ * DM);
}

// round 11
// speedup vs baseline: 1.2353x; 1.2353x over previous
#include <cuda_runtime.h>
#include <cuda_bf16.h>
#include <cuda_fp16.h>
#include <cstdint>

// ---------------------------------------------------------------------------
// Problem constants
// ---------------------------------------------------------------------------
#define BN   8
#define SEQ  2048
#define DIN  1024
#define DM   1024
#define NTOK (BN*SEQ)          // 16384

// ---------------------------------------------------------------------------
// Blocked fp16 operand layout (round-9 validated):
//   operand[row, k] stored as 32KB blocks indexed [row/256][k/64].
//   Block: 256 rows x 128B; row = 64 fp16 k-values, SW128-swizzled.
// Round-11: cluster of 2 CTAs = adjacent m-tiles sharing the same n-tile.
//   A: per-CTA unicast bulk copy. B: rank 0 multicasts to both (mask 0b11).
// ---------------------------------------------------------------------------
#define SWZ128(off) ((off) ^ (((off) >> 3) & 0x70))

__device__ uint8_t g_Xq[(size_t)NTOK*DIN*2];
__device__ uint8_t g_Xk[(size_t)NTOK*DIN*2];
__device__ uint8_t g_Xv[(size_t)NTOK*DIN*2];
__device__ uint8_t g_Wq[(size_t)DM*DIN*2];
__device__ uint8_t g_Wk[(size_t)DM*DIN*2];
__device__ uint8_t g_Wv[(size_t)DM*DIN*2];
__device__ uint8_t g_Qb[(size_t)NTOK*DM*2];          // 4MB/batch, nkc=16
__device__ uint8_t g_Kb[(size_t)NTOK*DM*2];
__device__ uint8_t g_Vt[(size_t)BN*DM*SEQ*2];        // rows=v, k=s, nkc=32, 4MB/batch
__device__ uint8_t g_Pb[(size_t)BN*SEQ*SEQ*2];       // rows=q, k=s, nkc=32, 8MB/batch
__device__ float   g_rs[(size_t)BN*SEQ];

// ---------------------------------------------------------------------------
// Helpers available on base compute_103
// ---------------------------------------------------------------------------
__device__ __forceinline__ uint32_t smem_u32(const void* p) {
    uint32_t a;
    asm("{ .reg .u64 t; cvta.to.shared.u64 t, %1; cvt.u32.u64 %0, t; }"
        : "=r"(a) : "l"(p));
    return a;
}
__device__ __forceinline__ uint32_t cluster_rank() {
    uint32_t r;
    asm("mov.u32 %0, %%cluster_ctarank;" : "=r"(r));
    return r;
}
#define CLUSTER_SYNC() do { \
    asm volatile("barrier.cluster.arrive.aligned;" ::: "memory"); \
    asm volatile("barrier.cluster.wait.aligned;"   ::: "memory"); \
} while (0)

__device__ __forceinline__ void cp16(uint32_t dst, const void* src) {
    asm volatile("cp.async.cg.shared.global [%0], [%1], 16;" :: "r"(dst), "l"(src));
}
#define CP_COMMIT()  asm volatile("cp.async.commit_group;" ::: "memory")
#define CP_WAIT(N)   asm volatile("cp.async.wait_group %0;" :: "n"(N) : "memory")

__device__ __forceinline__ void mma16816h(float* c, const uint32_t* a,
                                          uint32_t b0, uint32_t b1) {
    asm volatile(
        "mma.sync.aligned.m16n8k16.row.col.f32.f16.f16.f32 "
        "{%0,%1,%2,%3}, {%4,%5,%6,%7}, {%8,%9}, {%0,%1,%2,%3};"
        : "+f"(c[0]), "+f"(c[1]), "+f"(c[2]), "+f"(c[3])
        : "r"(a[0]), "r"(a[1]), "r"(a[2]), "r"(a[3]), "r"(b0), "r"(b1));
}

__device__ __forceinline__ uint32_t pkh2(__half a, __half b) {
    __half2 t; t.x = a; t.y = b;
    return *(uint32_t*)&t;
}
__device__ __forceinline__ void store_blk1(uint8_t* base, int row, int k,
                                           int nkc, float v) {
    const size_t blk = (((size_t)(row >> 8)) * nkc + (k >> 6)) << 15;
    const uint32_t off = (uint32_t)(row & 255) * 128 + (k & 63) * 2;
    *(__half*)(base + blk + SWZ128(off)) = __float2half(v);
}

// bulk copies: contiguous gmem -> smem, completion via mbarrier tx-bytes
__device__ __forceinline__ void bulk_ld(uint32_t dst, const void* src,
                                        uint32_t bytes, uint32_t mbar) {
    asm volatile(
        "cp.async.bulk.shared::cluster.global.mbarrier::complete_tx::bytes "
        "[%0], [%1], %2, [%3];"
        :: "r"(dst), "l"(src), "r"(bytes), "r"(mbar) : "memory");
}
__device__ __forceinline__ void bulk_mc(uint32_t dst, const void* src,
                                        uint32_t bytes, uint32_t mbar,
                                        uint16_t mask) {
    asm volatile(
        "cp.async.bulk.shared::cluster.global.mbarrier::complete_tx::bytes"
        ".multicast::cluster [%0], [%1], %2, [%3], %4;"
        :: "r"(dst), "l"(src), "r"(bytes), "r"(mbar), "h"(mask) : "memory");
}
#define MBAR_INIT(addr, cnt) \
    asm volatile("mbarrier.init.shared.b64 [%0], %1;" :: "r"((uint32_t)(addr)), "r"((uint32_t)(cnt)) : "memory")
#define MBAR_EXPECT(addr, tx) \
    asm volatile("mbarrier.arrive.expect_tx.shared.b64 _, [%0], %1;" :: "r"((uint32_t)(addr)), "r"((uint32_t)(tx)) : "memory")
#define MBAR_WAIT(mbar, par) do { \
    uint32_t _m = (uint32_t)(mbar), _p = (uint32_t)(par), _d; \
    asm volatile("{\n\t.reg .pred p;\n\t" \
        "mbarrier.try_wait.parity.acquire.cta.shared::cta.b64 p, [%1], %2;\n\t" \
        "selp.b32 %0, 1, 0, p;\n\t}" : "=r"(_d) : "r"(_m), "r"(_p) : "memory"); \
    if (!_d) { \
        asm volatile("{\n\t.reg .pred P1;\n\t" \
            "WL_%=:\n\t" \
            "mbarrier.try_wait.parity.acquire.cta.shared::cta.b64 P1, [%0], %1, 0x989680;\n\t" \
            "@P1 bra.uni WD_%=;\n\tbra.uni WL_%=;\n\tWD_%=:\n\t}" \
            :: "r"(_m), "r"(_p) : "memory"); \
    } \
} while (0)

// ---------------------------------------------------------------------------
// tcgen05 helpers — ONLY compiled when the build has a compute_103a pass.
// ---------------------------------------------------------------------------
#if defined(__CUDA_ARCH_FEAT_SM103_ALL)
__device__ __forceinline__ uint32_t elect_one_pred() {
    uint32_t pred;
    asm volatile(
        "{\n\t.reg .pred p;\n\t"
        "elect.sync _|p, 0xFFFFFFFF;\n\t"
        "selp.b32 %0, 1, 0, p;\n\t}"
        : "=r"(pred));
    return pred;
}
#define TCGEN05_ALLOC(a, n) \
    asm volatile("tcgen05.alloc.cta_group::1.sync.aligned.shared::cta.b32 [%0], %1;" \
        :: "r"((uint32_t)(a)), "r"((uint32_t)(n)) : "memory")
#define TCGEN05_RELINQUISH() \
    asm volatile("tcgen05.relinquish_alloc_permit.cta_group::1.sync.aligned;")
#define TCGEN05_DEALLOC(t, n) \
    asm volatile("tcgen05.dealloc.cta_group::1.sync.aligned.b32 %0, %1;" :: "r"(t), "r"((uint32_t)(n)))
#define TCGEN05_COMMIT_MC(m, mask) \
    asm volatile("tcgen05.commit.cta_group::1.mbarrier::arrive::one.shared::cluster.multicast::cluster.b64 [%0], %1;" \
        :: "r"((uint32_t)(m)), "h"((uint16_t)(mask)) : "memory")
#define TCGEN05_WAIT_LD()    asm volatile("tcgen05.wait::ld.sync.aligned;" ::: "memory")
#define TCGEN05_FENCE_AFTER() asm volatile("tcgen05.fence::after_thread_sync;" ::: "memory")
#define TCGEN05_LD_32X32B_X32(r, ta) \
    asm volatile( \
        "tcgen05.ld.sync.aligned.32x32b.x32.b32 " \
        "{%0, %1, %2, %3, %4, %5, %6, %7, " \
        " %8, %9, %10, %11, %12, %13, %14, %15, " \
        " %16, %17, %18, %19, %20, %21, %22, %23, " \
        " %24, %25, %26, %27, %28, %29, %30, %31}, [%32];" \
        : "=r"((r)[0]),  "=r"((r)[1]),  "=r"((r)[2]),  "=r"((r)[3]), \
          "=r"((r)[4]),  "=r"((r)[5]),  "=r"((r)[6]),  "=r"((r)[7]), \
          "=r"((r)[8]),  "=r"((r)[9]),  "=r"((r)[10]), "=r"((r)[11]), \
          "=r"((r)[12]), "=r"((r)[13]), "=r"((r)[14]), "=r"((r)[15]), \
          "=r"((r)[16]), "=r"((r)[17]), "=r"((r)[18]), "=r"((r)[19]), \
          "=r"((r)[20]), "=r"((r)[21]), "=r"((r)[22]), "=r"((r)[23]), \
          "=r"((r)[24]), "=r"((r)[25]), "=r"((r)[26]), "=r"((r)[27]), \
          "=r"((r)[28]), "=r"((r)[29]), "=r"((r)[30]), "=r"((r)[31]) \
        : "r"(ta))
static constexpr uint64_t SMEM_DESC_BASE_SW128 =
    (uint64_t(2)  << 61) | (uint64_t(1) << 46) | (uint64_t(64) << 32) | (uint64_t(1) << 16);
#define MAKE_SMEM_DESC(ba) (SMEM_DESC_BASE_SW128 | ((uint64_t)((ba) >> 4) & 0x3FFF))
__device__ __forceinline__ void mma_f16_ss(uint32_t d, uint64_t ad, uint64_t bd,
                                           uint32_t idesc, bool acc) {
    uint32_t en = acc ? 1u : 0u;
    asm volatile(
        "{\n\t.reg .pred p;\n\t"
        "setp.ne.u32 p, %5, 0;\n\t"
        "tcgen05.mma.cta_group::1.kind::f16 [%0], %1, %2, %3, {%4, %4, %4, %4}, p;\n\t"
        "}"
        :: "r"(d), "l"(ad), "l"(bd), "r"(idesc), "r"(0u), "r"(en)
        : "memory");
}
#endif  // __CUDA_ARCH_FEAT_SM103_ALL

// ---------------------------------------------------------------------------
// GEMM: C[M,N] = A[M,K] * B[N,K]^T, fp16 operands (blocked). Cluster of 2:
//   mTile = blockIdx.x (pair = adjacent x), nTile = blockIdx.y (shared).
//   A: per-CTA unicast bulk. B: rank0 multicasts 32KB blocks to both.
//   done[st]: rank1 commits MC to {self,rank0}; rank0 commits to self.
//   doneCnt: rank0=2, rank1=1. full[st] tx = 64KB both ranks.
//   Mainloop otherwise identical to round 9 (3-stage, deferred MMA wait).
// MODE 0: dual projection (z selects QK set), bias[n], nkc=16
// MODE 2: Vt = Wv * Xv^T (+bias[m]); nkc=32
// MODE 3: e=expf(acc*alpha) f16 out + row-sum atomics, nkc=32
// MODE 4: f32 out = acc / rowsum[m]
// ---------------------------------------------------------------------------
constexpr int OFF_B  = 32768;
constexpr int STAGE  = 65536;                     // 32KB A + 32KB B
constexpr int SMEM_DATA = 1024;
constexpr int SMEM_TOTAL = SMEM_DATA + 3 * STAGE; // 197632

template <int MODE>
__global__ void __launch_bounds__(256, 1) __cluster_dims__(2, 1, 1) tc_gemm(
    const uint8_t* __restrict__ Ab, const uint8_t* __restrict__ Bb,
    const uint8_t* __restrict__ A2b, const uint8_t* __restrict__ B2b,
    const float* __restrict__ bias, const float* __restrict__ bias2,
    float* __restrict__ Cf, uint8_t* __restrict__ Cb, uint8_t* __restrict__ C2b,
    float* __restrict__ rs,
    int K, float alpha,
    size_t sAb, size_t sBb, size_t sC)
{
    extern __shared__ char smem[];
    const int tid   = threadIdx.x;
    const size_t zb = blockIdx.z;
    const int m0    = blockIdx.x * 256;     // cluster pairs adjacent in m
    const int n0    = blockIdx.y * 256;     // shared within pair
    const int NC    = K >> 6;               // 64-k chunks

    if (MODE == 0 && zb == 1) {
        Ab = A2b; Bb = B2b; Cb = C2b; bias = bias2;
    }
    Ab += zb * sAb;  Bb += zb * sBb;
    const size_t blkA0 = ((size_t)(m0 >> 8)) * NC;
    const size_t blkB0 = ((size_t)(n0 >> 8)) * NC;

#if defined(__CUDA_ARCH_FEAT_SM103_ALL)
    // ======================= tcgen05 path (sm_103a) ========================
    const uint32_t sb = smem_u32(smem);
    const uint32_t rank = cluster_rank();
    const uint16_t doneMask = rank ? 0x3u : 0x1u;       // r1 -> both, r0 -> self
    const uint32_t doneCnt  = rank ? 1u : 2u;

    if (tid < 32) TCGEN05_ALLOC(sb + 0, 512);
    if (tid >= 32 && tid < 64) TCGEN05_RELINQUISH();
    if (tid == 0) {
#pragma unroll
        for (int s = 0; s < 3; ++s) {
            MBAR_INIT(sb + 8  + 8 * s, 1);         // full (tx-based)
            MBAR_INIT(sb + 32 + 8 * s, doneCnt);   // mma done
        }
    }
    __syncthreads();
    uint32_t tmem;
    asm volatile("ld.shared.b32 %0, [%1];" : "=r"(tmem) : "r"(sb + 0));

    constexpr uint32_t IDESC =
        (1u << 4) | ((256 / 8) << 17) | ((128 / 16) << 24);

    // pre-arm full[0..2] BEFORE any producer may load (B comes from rank 0)
    if (tid < 32 && elect_one_pred()) {
#pragma unroll
        for (int s = 0; s < 3; ++s) MBAR_EXPECT(sb + 8 + 8 * s, STAGE);
    }
    CLUSTER_SYNC();   // expects + barrier inits visible cluster-wide

    if (tid < 32 && elect_one_pred()) {
        auto load_chunk = [&](int kc, int st) {
            const uint32_t full = sb + 8 + 8 * st;
            const uint32_t base = sb + SMEM_DATA + st * STAGE;
            bulk_ld(base, Ab + ((blkA0 + kc) << 15), 32768, full);      // A self
            if (rank == 0)
                bulk_mc(base + OFF_B, Bb + ((blkB0 + kc) << 15), 32768,
                        full, 0x3);                                     // B both
        };

        load_chunk(0, 0);
        load_chunk(1, 1);
        load_chunk(2, 2);

        int fph[3] = {0, 0, 0}, dph[3] = {0, 0, 0};
        for (int c = 0; c < NC; ++c) {
            const int st = c % 3;
            MBAR_WAIT(sb + 8 + 8 * st, fph[st]);
            fph[st] ^= 1;
            // re-arm for chunk c+3 BEFORE committing (commit gates reloads)
            if (c + 3 < NC) MBAR_EXPECT(sb + 8 + 8 * st, STAGE);

            const uint32_t base = sb + SMEM_DATA + st * STAGE;
            const uint64_t daA0 = MAKE_SMEM_DESC(base);
            const uint64_t daA1 = MAKE_SMEM_DESC(base + 16384);
            const uint64_t db   = MAKE_SMEM_DESC(base + OFF_B);
#pragma unroll
            for (int half = 0; half < 2; ++half) {
                const uint64_t da = half ? daA1 : daA0;
                const uint32_t dt = tmem + half * 256;
#pragma unroll
                for (int ks = 0; ks < 4; ++ks)
                    mma_f16_ss(dt, da + ks * 2, db + ks * 2, IDESC,
                               !(c == 0 && ks == 0));
            }
            TCGEN05_COMMIT_MC(sb + 32 + 8 * st, doneMask);

            if (c > 0) {
                const int sp = (c - 1) % 3;
                MBAR_WAIT(sb + 32 + 8 * sp, dph[sp]);  // stage sp reusable
                dph[sp] ^= 1;
                if (c + 2 < NC) load_chunk(c + 2, sp);
            }
        }
        MBAR_WAIT(sb + 32 + 8 * ((NC - 1) % 3), dph[(NC - 1) % 3]);
    }
    __syncthreads();
    TCGEN05_FENCE_AFTER();

    // epilogue: warps 0-3 -> D0 (rows 0-127), warps 4-7 -> D1 (rows 128-255)
    {
        const int half = tid >> 7;
        const int w4   = (tid >> 5) & 3;
        const int lid  = tid & 31;
        const int m    = m0 + half * 128 + w4 * 32 + lid;
        const uint32_t dt = tmem + half * 256;
        float inv = 1.0f, lsum = 0.0f, bm = 0.0f;
        if (MODE == 4) inv = 1.0f / rs[zb * SEQ + m];
        if (MODE == 2) bm  = bias[m];
        for (int j0 = 0; j0 < 256; j0 += 32) {
            uint32_t r[32];
            TCGEN05_LD_32X32B_X32(r, dt + j0);
            TCGEN05_WAIT_LD();
            if (MODE == 4) {
                float4* dst = (float4*)(Cf + zb * sC + (size_t)m * DM + n0 + j0);
#pragma unroll
                for (int i = 0; i < 8; ++i) {
                    float4 v;
                    v.x = __uint_as_float(r[4 * i + 0]) * inv;
                    v.y = __uint_as_float(r[4 * i + 1]) * inv;
                    v.z = __uint_as_float(r[4 * i + 2]) * inv;
                    v.w = __uint_as_float(r[4 * i + 3]) * inv;
                    dst[i] = v;
                }
            } else {   // MODE 0 / 2 / 3: blocked fp16 store (32 vals = 64B)
                uint32_t H[16];
#pragma unroll
                for (int i = 0; i < 32; i += 2) {
                    float v0, v1;
                    if (MODE == 3) {
                        v0 = __expf(__uint_as_float(r[i])     * alpha);
                        v1 = __expf(__uint_as_float(r[i + 1]) * alpha);
                        lsum += v0 + v1;
                    } else if (MODE == 0) {
                        v0 = __uint_as_float(r[i])     + bias[n0 + j0 + i];
                        v1 = __uint_as_float(r[i + 1]) + bias[n0 + j0 + i + 1];
                    } else {
                        v0 = __uint_as_float(r[i])     + bm;
                        v1 = __uint_as_float(r[i + 1]) + bm;
                    }
                    H[i >> 1] = pkh2(__float2half(v0), __float2half(v1));
                }
                uint8_t* base;
                size_t blk;
                const int row = m & 255;
                if (MODE == 0) {          // Q/K: 4MB/batch(by m), nkc = 16
                    base = Cb + (size_t)(m >> 11) * 4194304u;
                    blk  = ((((size_t)((m & 2047) >> 8)) * 16) + ((n0 + j0) >> 6)) << 15;
                } else if (MODE == 3) {   // P: 8MB/batch, nkc = 32
                    base = Cb + zb * 8388608u;
                    blk  = ((((size_t)(m >> 8)) * 32) + ((n0 + j0) >> 6)) << 15;
                } else {                  // Vt: 4MB/batch, nkc = 32
                    base = Cb + zb * 4194304u;
                    blk  = ((((size_t)(m >> 8)) * 32) + ((n0 + j0) >> 6)) << 15;
                }
                const uint32_t u0 = (uint32_t)(((n0 + j0) & 63) >> 3);  // 0 or 4
#pragma unroll
                for (int q = 0; q < 4; ++q) {
                    uint4 hv;
                    hv.x = H[4*q]; hv.y = H[4*q+1]; hv.z = H[4*q+2]; hv.w = H[4*q+3];
                    *(uint4*)(base + blk +
                              SWZ128((uint32_t)row * 128 + (u0 + q) * 16)) = hv;
                }
            }
        }
        if (MODE == 3) atomicAdd(&rs[zb * SEQ + m], lsum);
    }
    __syncthreads();
    if (tid < 32) TCGEN05_DEALLOC(tmem, 512);
    CLUSTER_SYNC();   // no CTA exits while peer multicasts may target its smem

#elif defined(__CUDA_ARCH__)
    // ================= mma.sync fallback (base compute_103) =================
    // Correctness insurance only; no multicast (direct per-CTA loads).
    constexpr int STR = 20;
    constexpr int TILE_W = 128 * STR;
    constexpr int STAGE_W = 2 * TILE_W;
    const uint32_t sbase = smem_u32(smem);
    const int lane = tid & 31, wid = tid >> 5;
    const int wm = wid >> 1, wn = wid & 1;
    const int g = lane >> 2, tg = lane & 3;
    const int NC32 = K >> 5;

    auto load_chunk = [&](int c32, int st, int mbase, int nbase) {
        const int q = tid & 3, r0 = tid >> 2;
        const uint32_t dst0 = sbase + st * STAGE_W * 4;
        const int kc = c32 >> 1, h = c32 & 1;
#pragma unroll
        for (int i = 0; i < 2; ++i) {
            const int ra = mbase + r0 + 64 * i;
            const int rb = nbase + r0 + 64 * i;
            const uint32_t ro = (uint32_t)((r0 + 64 * i) * STR + q * 4) * 4;
            const size_t ba = (((size_t)(ra >> 8)) * NC + kc) << 15;
            const size_t bb = (((size_t)(rb >> 8)) * NC + kc) << 15;
            const uint32_t oa = (uint32_t)(ra & 255) * 128 + h * 64 + q * 16;
            const uint32_t ob = (uint32_t)(rb & 255) * 128 + h * 64 + q * 16;
            cp16(dst0 + ro,                Ab + ba + SWZ128(oa));
            cp16(dst0 + TILE_W * 4 + ro,   Bb + bb + SWZ128(ob));
        }
    };

    for (int mh = 0; mh < 2; ++mh) {
        const int mb0 = m0 + mh * 128;
        for (int np = 0; np < 2; ++np) {
            const int nb0 = n0 + np * 128;

            float acc[2][8][4];
#pragma unroll
            for (int a = 0; a < 2; ++a)
#pragma unroll
                for (int b = 0; b < 8; ++b)
#pragma unroll
                    for (int c = 0; c < 4; ++c) acc[a][b][c] = 0.0f;

            load_chunk(0, 0, mb0, nb0); CP_COMMIT();

            for (int c = 0; c < NC32; ++c) {
                const int st = c & 1;
                if (c + 1 < NC32) { load_chunk(c + 1, st ^ 1, mb0, nb0); CP_COMMIT(); CP_WAIT(1); }
                else              { CP_WAIT(0); }
                __syncthreads();

                const uint32_t* s0 = (const uint32_t*)smem + st * STAGE_W;
#pragma unroll
                for (int ks = 0; ks < 2; ++ks) {
                    uint32_t af[2][4];
#pragma unroll
                    for (int mt = 0; mt < 2; ++mt) {
                        const int rb = wm * 32 + mt * 16;
                        const uint32_t* pa = s0 + (rb + g) * STR + ks * 8 + tg;
                        af[mt][0] = pa[0];           af[mt][2] = pa[4];
                        af[mt][1] = pa[8 * STR];     af[mt][3] = pa[8 * STR + 4];
                    }
#pragma unroll
                    for (int nt = 0; nt < 8; ++nt) {
                        const int nb = wn * 64 + nt * 8;
                        const uint32_t* pb = s0 + TILE_W + (nb + g) * STR + ks * 8 + tg;
                        const uint32_t b0 = pb[0], b1 = pb[4];
#pragma unroll
                        for (int mt = 0; mt < 2; ++mt)
                            mma16816h(acc[mt][nt], af[mt], b0, b1);
                    }
                }
                __syncthreads();
            }

#pragma unroll
            for (int mt = 0; mt < 2; ++mt) {
#pragma unroll
                for (int nt = 0; nt < 8; ++nt) {
                    const int m1 = mb0 + wm * 32 + mt * 16 + g;
                    const int m2 = m1 + 8;
                    const int n  = nb0 + wn * 64 + nt * 8 + tg * 2;
                    const float* a = acc[mt][nt];
                    if (MODE == 4) {
                        const float i1 = 1.0f / rs[zb * SEQ + m1];
                        const float i2 = 1.0f / rs[zb * SEQ + m2];
                        float2 v0; v0.x = a[0] * i1; v0.y = a[1] * i1;
                        float2 v1; v1.x = a[2] * i2; v1.y = a[3] * i2;
                        *(float2*)(Cf + zb * sC + (size_t)m1 * DM + n) = v0;
                        *(float2*)(Cf + zb * sC + (size_t)m2 * DM + n) = v1;
                    } else if (MODE == 0) {
#pragma unroll
                        for (int e = 0; e < 4; ++e) {
                            const int m = (e < 2) ? m1 : m2;
                            const int nn = n + (e & 1);
                            store_blk1(Cb + (size_t)(m >> 11) * 4194304u,
                                       m & 2047, nn, 16, a[e] + bias[nn]);
                        }
                    } else if (MODE == 3) {
                        float e0 = __expf(a[0] * alpha), e1 = __expf(a[1] * alpha);
                        float e2 = __expf(a[2] * alpha), e3 = __expf(a[3] * alpha);
                        atomicAdd(&rs[zb * SEQ + m1], e0 + e1);
                        atomicAdd(&rs[zb * SEQ + m2], e2 + e3);
                        uint8_t* base = Cb + zb * 8388608u;
                        store_blk1(base, m1, n,     32, e0);
                        store_blk1(base, m1, n + 1, 32, e1);
                        store_blk1(base, m2, n,     32, e2);
                        store_blk1(base, m2, n + 1, 32, e3);
                    } else {  // MODE 2
                        uint8_t* base = Cb + zb * 4194304u;
#pragma unroll
                        for (int e = 0; e < 4; ++e) {
                            const int m = (e < 2) ? m1 : m2;
                            const int nn = n + (e & 1);
                            store_blk1(base, m, nn, 32, a[e] + bias[m]);
                        }
                    }
                }
            }
            __syncthreads();
        }
    }
#endif
}

// ---------------------------------------------------------------------------
// f32 -> blocked fp16 (K fixed = 1024; nkc = 16). z selects among 3 tensors.
// ---------------------------------------------------------------------------
__global__ void __launch_bounds__(256) split3_k(
    const float* __restrict__ x0, const float* __restrict__ x1,
    const float* __restrict__ x2,
    uint8_t* __restrict__ d0, uint8_t* __restrict__ d1,
    uint8_t* __restrict__ d2, int nunits)
{
    const int z = blockIdx.z;
    const float* x = (z == 0) ? x0 : (z == 1) ? x1 : x2;
    uint8_t*   dst = (z == 0) ? d0 : (z == 1) ? d1 : d2;
    for (int u = blockIdx.x * 256 + threadIdx.x; u < nunits; u += gridDim.x * 256) {
        const int r = u >> 7;
        const int j = u & 127;
        const float4 f0 = *(const float4*)(x + ((size_t)r << 10) + (j << 3));
        const float4 f1 = *(const float4*)(x + ((size_t)r << 10) + (j << 3) + 4);
        uint4 hv;
        hv.x = pkh2(__float2half(f0.x), __float2half(f0.y));
        hv.y = pkh2(__float2half(f0.z), __float2half(f0.w));
        hv.z = pkh2(__float2half(f1.x), __float2half(f1.y));
        hv.w = pkh2(__float2half(f1.z), __float2half(f1.w));
        const size_t blk = ((((size_t)(r >> 8)) << 4) + (j >> 3)) << 15;  // nkc=16
        const uint32_t ro = (uint32_t)(r & 255) * 128 + (j & 7) * 16;
        *(uint4*)(dst + blk + SWZ128(ro)) = hv;
    }
}

__global__ void __launch_bounds__(1024) zero_k(float* __restrict__ p, int n)
{
    int i = blockIdx.x * 1024 + threadIdx.x;
    if (i < n) p[i] = 0.0f;
}

// ---------------------------------------------------------------------------
extern "C" void kernel_launch(void* const* d_in, const int* in_sizes, int n_in,
                              void* d_out, int out_size)
{
    (void)in_sizes; (void)n_in; (void)out_size;
    const float* q  = (const float*)d_in[0];
    const float* kx = (const float*)d_in[1];
    const float* vx = (const float*)d_in[2];
    const float* Wq = (const float*)d_in[3];
    const float* bq = (const float*)d_in[4];
    const float* Wk = (const float*)d_in[5];
    const float* bk = (const float*)d_in[6];
    const float* Wv = (const float*)d_in[7];
    const float* bv = (const float*)d_in[8];
    float* out = (float*)d_out;

    uint8_t *Xq, *Xk, *Xv, *Wqb, *Wkb, *Wvb, *Qb, *Kb, *Vt, *Pb;
    float* rs;
    cudaGetSymbolAddress((void**)&Xq,  g_Xq);  cudaGetSymbolAddress((void**)&Xk,  g_Xk);
    cudaGetSymbolAddress((void**)&Xv,  g_Xv);
    cudaGetSymbolAddress((void**)&Wqb, g_Wq);  cudaGetSymbolAddress((void**)&Wkb, g_Wk);
    cudaGetSymbolAddress((void**)&Wvb, g_Wv);
    cudaGetSymbolAddress((void**)&Qb,  g_Qb);  cudaGetSymbolAddress((void**)&Kb,  g_Kb);
    cudaGetSymbolAddress((void**)&Vt,  g_Vt);  cudaGetSymbolAddress((void**)&Pb,  g_Pb);
    cudaGetSymbolAddress((void**)&rs,  g_rs);

    cudaFuncSetAttribute(tc_gemm<0>, cudaFuncAttributeMaxDynamicSharedMemorySize, SMEM_TOTAL);
    cudaFuncSetAttribute(tc_gemm<2>, cudaFuncAttributeMaxDynamicSharedMemorySize, SMEM_TOTAL);
    cudaFuncSetAttribute(tc_gemm<3>, cudaFuncAttributeMaxDynamicSharedMemorySize, SMEM_TOTAL);
    cudaFuncSetAttribute(tc_gemm<4>, cudaFuncAttributeMaxDynamicSharedMemorySize, SMEM_TOTAL);

    // 1. splits (inputs, weights) + zero row sums
    split3_k<<<dim3(2048, 1, 3), 256>>>(q, kx, vx, Xq, Xk, Xv, NTOK * DIN / 8);
    split3_k<<<dim3(512,  1, 3), 256>>>(Wq, Wk, Wv, Wqb, Wkb, Wvb, DM * DIN / 8);
    zero_k<<<(BN * SEQ + 1023) / 1024, 1024>>>(rs, BN * SEQ);

    // grid: x = mTiles (cluster pairs adjacent), y = nTiles, z = batch/set
    // 2. Q and K projections in ONE launch
    tc_gemm<0><<<dim3(NTOK / 256, DM / 256, 2), 256, SMEM_TOTAL>>>(
        Xq, Wqb, Xk, Wkb, bq, bk, nullptr, Qb, Kb, nullptr,
        DIN, 1.0f, 0, 0, 0);

    // 3. Vt = Wv * Xv^T (+bv)
    tc_gemm<2><<<dim3(DM / 256, SEQ / 256, BN), 256, SMEM_TOTAL>>>(
        Wvb, Xv, nullptr, nullptr, bv, nullptr, nullptr, Vt, nullptr, nullptr,
        DIN, 1.0f, 0, 4194304u, 0);

    // 4. scores + exp + row sums -> fp16 P
    tc_gemm<3><<<dim3(SEQ / 256, SEQ / 256, BN), 256, SMEM_TOTAL>>>(
        Qb, Kb, nullptr, nullptr, nullptr, nullptr, nullptr, Pb, nullptr, rs,
        DM, 0.03125f, 4194304u, 4194304u, 0);

    // 5. O = (P * Vt^T) / rowsum
    tc_gemm<4><<<dim3(SEQ / 256, DM / 256, BN), 256, SMEM_TOTAL>>>(
        Pb, Vt, nullptr, nullptr, nullptr, nullptr, out, nullptr, nullptr, rs,
        SEQ, 1.0f, 8388608u, 4194304u, (size_t)SEQ * DM);
}

// round 12
// speedup vs baseline: 1.3220x; 1.0701x over previous
#include <cuda_runtime.h>
#include <cuda_bf16.h>
#include <cuda_fp16.h>
#include <cstdint>

// ---------------------------------------------------------------------------
// Problem constants
// ---------------------------------------------------------------------------
#define BN   8
#define SEQ  2048
#define DIN  1024
#define DM   1024
#define NTOK (BN*SEQ)          // 16384

// ---------------------------------------------------------------------------
// Blocked fp16 operand layout (round-9 validated):
//   operand[row, k] stored as 32KB blocks indexed [row/256][k/64].
//   Block: 256 rows x 128B; row = 64 fp16 k-values, SW128-swizzled.
//   GEMM chunk (K=64) load = TWO contiguous 32KB cp.async.bulk copies.
// NO clusters (rounds 10/11 proved cross-CTA coupling costs > L2 reuse gain).
// ---------------------------------------------------------------------------
#define SWZ128(off) ((off) ^ (((off) >> 3) & 0x70))

__device__ uint8_t g_Xq[(size_t)NTOK*DIN*2];
__device__ uint8_t g_Xk[(size_t)NTOK*DIN*2];
__device__ uint8_t g_Xv[(size_t)NTOK*DIN*2];
__device__ uint8_t g_Wq[(size_t)DM*DIN*2];
__device__ uint8_t g_Wk[(size_t)DM*DIN*2];
__device__ uint8_t g_Wv[(size_t)DM*DIN*2];
__device__ uint8_t g_Qb[(size_t)NTOK*DM*2];          // 4MB/batch, nkc=16
__device__ uint8_t g_Kb[(size_t)NTOK*DM*2];
__device__ uint8_t g_Vt[(size_t)BN*DM*SEQ*2];        // rows=v, k=s, nkc=32, 4MB/batch
__device__ uint8_t g_Pb[(size_t)BN*SEQ*SEQ*2];       // rows=q, k=s, nkc=32, 8MB/batch
__device__ float   g_rs[(size_t)BN*SEQ];

// ---------------------------------------------------------------------------
// Helpers available on base compute_103
// ---------------------------------------------------------------------------
__device__ __forceinline__ uint32_t smem_u32(const void* p) {
    uint32_t a;
    asm("{ .reg .u64 t; cvta.to.shared.u64 t, %1; cvt.u32.u64 %0, t; }"
        : "=r"(a) : "l"(p));
    return a;
}
__device__ __forceinline__ void cp16(uint32_t dst, const void* src) {
    asm volatile("cp.async.cg.shared.global [%0], [%1], 16;" :: "r"(dst), "l"(src));
}
#define CP_COMMIT()  asm volatile("cp.async.commit_group;" ::: "memory")
#define CP_WAIT(N)   asm volatile("cp.async.wait_group %0;" :: "n"(N) : "memory")

__device__ __forceinline__ void mma16816h(float* c, const uint32_t* a,
                                          uint32_t b0, uint32_t b1) {
    asm volatile(
        "mma.sync.aligned.m16n8k16.row.col.f32.f16.f16.f32 "
        "{%0,%1,%2,%3}, {%4,%5,%6,%7}, {%8,%9}, {%0,%1,%2,%3};"
        : "+f"(c[0]), "+f"(c[1]), "+f"(c[2]), "+f"(c[3])
        : "r"(a[0]), "r"(a[1]), "r"(a[2]), "r"(a[3]), "r"(b0), "r"(b1));
}

__device__ __forceinline__ uint32_t pkh2(__half a, __half b) {
    __half2 t; t.x = a; t.y = b;
    return *(uint32_t*)&t;
}
// scalar fp16 store into blocked layout (fallback path)
__device__ __forceinline__ void store_blk1(uint8_t* base, int row, int k,
                                           int nkc, float v) {
    const size_t blk = (((size_t)(row >> 8)) * nkc + (k >> 6)) << 15;
    const uint32_t off = (uint32_t)(row & 255) * 128 + (k & 63) * 2;
    *(__half*)(base + blk + SWZ128(off)) = __float2half(v);
}

// bulk copy (UBLKCP): contiguous gmem -> smem, completion via mbarrier tx-bytes
__device__ __forceinline__ void bulk_ld(uint32_t dst, const void* src,
                                        uint32_t bytes, uint32_t mbar) {
    asm volatile(
        "cp.async.bulk.shared::cluster.global.mbarrier::complete_tx::bytes "
        "[%0], [%1], %2, [%3];"
        :: "r"(dst), "l"(src), "r"(bytes), "r"(mbar) : "memory");
}
#define MBAR_INIT(addr, cnt) \
    asm volatile("mbarrier.init.shared.b64 [%0], %1;" :: "r"((uint32_t)(addr)), "r"((uint32_t)(cnt)) : "memory")
#define MBAR_EXPECT(addr, tx) \
    asm volatile("mbarrier.arrive.expect_tx.shared.b64 _, [%0], %1;" :: "r"((uint32_t)(addr)), "r"((uint32_t)(tx)) : "memory")
#define MBAR_WAIT(mbar, par) do { \
    uint32_t _m = (uint32_t)(mbar), _p = (uint32_t)(par), _d; \
    asm volatile("{\n\t.reg .pred p;\n\t" \
        "mbarrier.try_wait.parity.acquire.cta.shared::cta.b64 p, [%1], %2;\n\t" \
        "selp.b32 %0, 1, 0, p;\n\t}" : "=r"(_d) : "r"(_m), "r"(_p) : "memory"); \
    if (!_d) { \
        asm volatile("{\n\t.reg .pred P1;\n\t" \
            "WL_%=:\n\t" \
            "mbarrier.try_wait.parity.acquire.cta.shared::cta.b64 P1, [%0], %1, 0x989680;\n\t" \
            "@P1 bra.uni WD_%=;\n\tbra.uni WL_%=;\n\tWD_%=:\n\t}" \
            :: "r"(_m), "r"(_p) : "memory"); \
    } \
} while (0)

// ---------------------------------------------------------------------------
// tcgen05 helpers — ONLY compiled when the build has a compute_103a pass.
// ---------------------------------------------------------------------------
#if defined(__CUDA_ARCH_FEAT_SM103_ALL)
__device__ __forceinline__ uint32_t elect_one_pred() {
    uint32_t pred;
    asm volatile(
        "{\n\t.reg .pred p;\n\t"
        "elect.sync _|p, 0xFFFFFFFF;\n\t"
        "selp.b32 %0, 1, 0, p;\n\t}"
        : "=r"(pred));
    return pred;
}
#define TCGEN05_ALLOC(a, n) \
    asm volatile("tcgen05.alloc.cta_group::1.sync.aligned.shared::cta.b32 [%0], %1;" \
        :: "r"((uint32_t)(a)), "r"((uint32_t)(n)) : "memory")
#define TCGEN05_RELINQUISH() \
    asm volatile("tcgen05.relinquish_alloc_permit.cta_group::1.sync.aligned;")
#define TCGEN05_DEALLOC(t, n) \
    asm volatile("tcgen05.dealloc.cta_group::1.sync.aligned.b32 %0, %1;" :: "r"(t), "r"((uint32_t)(n)))
#define TCGEN05_COMMIT(m) \
    asm volatile("tcgen05.commit.cta_group::1.mbarrier::arrive::one.shared::cluster.b64 [%0];" \
        :: "r"((uint32_t)(m)) : "memory")
#define TCGEN05_WAIT_LD()    asm volatile("tcgen05.wait::ld.sync.aligned;" ::: "memory")
#define TCGEN05_FENCE_AFTER() asm volatile("tcgen05.fence::after_thread_sync;" ::: "memory")
#define TCGEN05_LD_32X32B_X32(r, ta) \
    asm volatile( \
        "tcgen05.ld.sync.aligned.32x32b.x32.b32 " \
        "{%0, %1, %2, %3, %4, %5, %6, %7, " \
        " %8, %9, %10, %11, %12, %13, %14, %15, " \
        " %16, %17, %18, %19, %20, %21, %22, %23, " \
        " %24, %25, %26, %27, %28, %29, %30, %31}, [%32];" \
        : "=r"((r)[0]),  "=r"((r)[1]),  "=r"((r)[2]),  "=r"((r)[3]), \
          "=r"((r)[4]),  "=r"((r)[5]),  "=r"((r)[6]),  "=r"((r)[7]), \
          "=r"((r)[8]),  "=r"((r)[9]),  "=r"((r)[10]), "=r"((r)[11]), \
          "=r"((r)[12]), "=r"((r)[13]), "=r"((r)[14]), "=r"((r)[15]), \
          "=r"((r)[16]), "=r"((r)[17]), "=r"((r)[18]), "=r"((r)[19]), \
          "=r"((r)[20]), "=r"((r)[21]), "=r"((r)[22]), "=r"((r)[23]), \
          "=r"((r)[24]), "=r"((r)[25]), "=r"((r)[26]), "=r"((r)[27]), \
          "=r"((r)[28]), "=r"((r)[29]), "=r"((r)[30]), "=r"((r)[31]) \
        : "r"(ta))
static constexpr uint64_t SMEM_DESC_BASE_SW128 =
    (uint64_t(2)  << 61) | (uint64_t(1) << 46) | (uint64_t(64) << 32) | (uint64_t(1) << 16);
#define MAKE_SMEM_DESC(ba) (SMEM_DESC_BASE_SW128 | ((uint64_t)((ba) >> 4) & 0x3FFF))
__device__ __forceinline__ void mma_f16_ss(uint32_t d, uint64_t ad, uint64_t bd,
                                           uint32_t idesc, bool acc) {
    uint32_t en = acc ? 1u : 0u;
    asm volatile(
        "{\n\t.reg .pred p;\n\t"
        "setp.ne.u32 p, %5, 0;\n\t"
        "tcgen05.mma.cta_group::1.kind::f16 [%0], %1, %2, %3, {%4, %4, %4, %4}, p;\n\t"
        "}"
        :: "r"(d), "l"(ad), "l"(bd), "r"(idesc), "r"(0u), "r"(en)
        : "memory");
}
#endif  // __CUDA_ARCH_FEAT_SM103_ALL

// ---------------------------------------------------------------------------
// GEMM: C[M,N] = A[M,K] * B[N,K]^T, single-pass fp16 operands (blocked).
// tcgen05: CTA 256x256, TK=64, two M=128 TMEM accumulators, 3-stage pipeline,
// 2x32KB bulk loads/chunk, single-elected-thread mainloop, deferred MMA wait.
// Epilogue: paired LDTM.x32 (one wait per 64 columns).
// MODE 0: dual projection (z selects {Xq,Wq,bq,Qb}/{Xk,Wk,bk,Kb}), bias[n], nkc=16
// MODE 2: Vt = Wv * Xv^T (+bias[m]); out rows=v, k=s, nkc=32
// MODE 3: e=expf(acc*alpha) f16 out + row-sum atomics [scores->P], nkc=32
// MODE 4: f32 out = acc / rowsum[m]  [PV]
// ---------------------------------------------------------------------------
constexpr int OFF_B  = 32768;
constexpr int STAGE  = 65536;                     // 32KB A + 32KB B
constexpr int SMEM_DATA = 1024;
constexpr int SMEM_TOTAL = SMEM_DATA + 3 * STAGE; // 197632

template <int MODE>
__global__ void __launch_bounds__(256, 1) tc_gemm(
    const uint8_t* __restrict__ Ab, const uint8_t* __restrict__ Bb,
    const uint8_t* __restrict__ A2b, const uint8_t* __restrict__ B2b,
    const float* __restrict__ bias, const float* __restrict__ bias2,
    float* __restrict__ Cf, uint8_t* __restrict__ Cb, uint8_t* __restrict__ C2b,
    float* __restrict__ rs,
    int K, float alpha,
    size_t sAb, size_t sBb, size_t sC)
{
    extern __shared__ char smem[];
    const int tid   = threadIdx.x;
    const size_t zb = blockIdx.z;
    const int m0    = blockIdx.y * 256;
    const int n0    = blockIdx.x * 256;
    const int NC    = K >> 6;                 // 64-k chunks

    if (MODE == 0 && zb == 1) {
        Ab = A2b; Bb = B2b; Cb = C2b; bias = bias2;
    }
    Ab += zb * sAb;  Bb += zb * sBb;
    const size_t blkA0 = ((size_t)(m0 >> 8)) * NC;
    const size_t blkB0 = ((size_t)(n0 >> 8)) * NC;

#if defined(__CUDA_ARCH_FEAT_SM103_ALL)
    // ======================= tcgen05 path (sm_103a) ========================
    const uint32_t sb = smem_u32(smem);

    if (tid < 32) TCGEN05_ALLOC(sb + 0, 512);
    if (tid >= 32 && tid < 64) TCGEN05_RELINQUISH();
    if (tid == 0) {
#pragma unroll
        for (int s = 0; s < 3; ++s) {
            MBAR_INIT(sb + 8  + 8 * s, 1);   // full (tx-based)
            MBAR_INIT(sb + 32 + 8 * s, 1);   // mma done
        }
    }
    __syncthreads();
    uint32_t tmem;
    asm volatile("ld.shared.b32 %0, [%1];" : "=r"(tmem) : "r"(sb + 0));

    // kind::f16, atype=btype=F16 (0), dtype F32, N=256, M=128 per dispatch
    constexpr uint32_t IDESC =
        (1u << 4) | ((256 / 8) << 17) | ((128 / 16) << 24);

    if (tid < 32 && elect_one_pred()) {
        auto load_chunk = [&](int kc, int st) {
            const uint32_t full = sb + 8 + 8 * st;
            const uint32_t base = sb + SMEM_DATA + st * STAGE;
            MBAR_EXPECT(full, STAGE);
            bulk_ld(base,         Ab + ((blkA0 + kc) << 15), 32768, full);
            bulk_ld(base + OFF_B, Bb + ((blkB0 + kc) << 15), 32768, full);
        };

        load_chunk(0, 0);
        if (NC > 1) load_chunk(1, 1);
        if (NC > 2) load_chunk(2, 2);

        int fph[3] = {0, 0, 0}, mph[3] = {0, 0, 0};
        for (int c = 0; c < NC; ++c) {
            const int st = c % 3;
            MBAR_WAIT(sb + 8 + 8 * st, fph[st]);
            fph[st] ^= 1;

            const uint32_t base = sb + SMEM_DATA + st * STAGE;
            const uint64_t daA0 = MAKE_SMEM_DESC(base);
            const uint64_t daA1 = MAKE_SMEM_DESC(base + 16384);
            const uint64_t db   = MAKE_SMEM_DESC(base + OFF_B);
#pragma unroll
            for (int half = 0; half < 2; ++half) {
                const uint64_t da = half ? daA1 : daA0;
                const uint32_t dt = tmem + half * 256;
#pragma unroll
                for (int ks = 0; ks < 4; ++ks)   // 16 fp16 per step = +2 units
                    mma_f16_ss(dt, da + ks * 2, db + ks * 2, IDESC,
                               !(c == 0 && ks == 0));
            }
            TCGEN05_COMMIT(sb + 32 + 8 * st);

            if (c > 0) {
                const int sp = (c - 1) % 3;
                MBAR_WAIT(sb + 32 + 8 * sp, mph[sp]);
                mph[sp] ^= 1;
                if (c + 2 < NC) load_chunk(c + 2, sp);
            }
        }
        MBAR_WAIT(sb + 32 + 8 * ((NC - 1) % 3), mph[(NC - 1) % 3]);
    }
    __syncthreads();
    TCGEN05_FENCE_AFTER();

    // epilogue: warps 0-3 -> D0 (rows 0-127), warps 4-7 -> D1 (rows 128-255)
    // paired x32 loads: one tcgen05.wait per 64 columns (aligned to 32KB block)
    {
        const int half = tid >> 7;
        const int w4   = (tid >> 5) & 3;
        const int lid  = tid & 31;
        const int m    = m0 + half * 128 + w4 * 32 + lid;
        const uint32_t dt = tmem + half * 256;
        float inv = 1.0f, lsum = 0.0f, bm = 0.0f;
        if (MODE == 4) inv = 1.0f / rs[zb * SEQ + m];
        if (MODE == 2) bm  = bias[m];
        for (int j0 = 0; j0 < 256; j0 += 64) {
            uint32_t r[64];
            TCGEN05_LD_32X32B_X32(r,      dt + j0);
            TCGEN05_LD_32X32B_X32(r + 32, dt + j0 + 32);
            TCGEN05_WAIT_LD();
            if (MODE == 4) {
                float4* dst = (float4*)(Cf + zb * sC + (size_t)m * DM + n0 + j0);
#pragma unroll
                for (int i = 0; i < 16; ++i) {
                    float4 v;
                    v.x = __uint_as_float(r[4 * i + 0]) * inv;
                    v.y = __uint_as_float(r[4 * i + 1]) * inv;
                    v.z = __uint_as_float(r[4 * i + 2]) * inv;
                    v.w = __uint_as_float(r[4 * i + 3]) * inv;
                    dst[i] = v;
                }
            } else {   // MODE 0 / 2 / 3: blocked fp16 store (64 vals = 128B row)
                uint32_t H[32];
#pragma unroll
                for (int i = 0; i < 64; i += 2) {
                    float v0, v1;
                    if (MODE == 3) {
                        v0 = __expf(__uint_as_float(r[i])     * alpha);
                        v1 = __expf(__uint_as_float(r[i + 1]) * alpha);
                        lsum += v0 + v1;
                    } else if (MODE == 0) {
                        v0 = __uint_as_float(r[i])     + bias[n0 + j0 + i];
                        v1 = __uint_as_float(r[i + 1]) + bias[n0 + j0 + i + 1];
                    } else {
                        v0 = __uint_as_float(r[i])     + bm;
                        v1 = __uint_as_float(r[i + 1]) + bm;
                    }
                    H[i >> 1] = pkh2(__float2half(v0), __float2half(v1));
                }
                uint8_t* base;
                size_t blk;
                const int row = m & 255;
                if (MODE == 0) {          // Q/K: 4MB/batch(by m), nkc = 16
                    base = Cb + (size_t)(m >> 11) * 4194304u;
                    blk  = ((((size_t)((m & 2047) >> 8)) * 16) + ((n0 + j0) >> 6)) << 15;
                } else if (MODE == 3) {   // P: 8MB/batch, nkc = 32
                    base = Cb + zb * 8388608u;
                    blk  = ((((size_t)(m >> 8)) * 32) + ((n0 + j0) >> 6)) << 15;
                } else {                  // Vt: 4MB/batch, nkc = 32
                    base = Cb + zb * 4194304u;
                    blk  = ((((size_t)(m >> 8)) * 32) + ((n0 + j0) >> 6)) << 15;
                }
#pragma unroll
                for (int q = 0; q < 8; ++q) {
                    uint4 hv;
                    hv.x = H[4*q]; hv.y = H[4*q+1]; hv.z = H[4*q+2]; hv.w = H[4*q+3];
                    *(uint4*)(base + blk +
                              SWZ128((uint32_t)row * 128 + q * 16)) = hv;
                }
            }
        }
        if (MODE == 3) atomicAdd(&rs[zb * SEQ + m], lsum);
    }
    __syncthreads();
    if (tid < 32) TCGEN05_DEALLOC(tmem, 512);

#elif defined(__CUDA_ARCH__)
    // ================= mma.sync fallback (base compute_103) =================
    // Correctness insurance only (sm_103a cubin is the one that runs).
    constexpr int STR = 20;                 // words per 32-fp16 sub-row (padded)
    constexpr int TILE_W = 128 * STR;
    constexpr int STAGE_W = 2 * TILE_W;     // A tile + B tile
    const uint32_t sbase = smem_u32(smem);
    const int lane = tid & 31, wid = tid >> 5;
    const int wm = wid >> 1, wn = wid & 1;
    const int g = lane >> 2, tg = lane & 3;
    const int NC32 = K >> 5;

    auto load_chunk = [&](int c32, int st, int mbase, int nbase) {
        const int q = tid & 3, r0 = tid >> 2;
        const uint32_t dst0 = sbase + st * STAGE_W * 4;
        const int kc = c32 >> 1, h = c32 & 1;
#pragma unroll
        for (int i = 0; i < 2; ++i) {
            const int ra = mbase + r0 + 64 * i;
            const int rb = nbase + r0 + 64 * i;
            const uint32_t ro = (uint32_t)((r0 + 64 * i) * STR + q * 4) * 4;
            const size_t ba = (((size_t)(ra >> 8)) * NC + kc) << 15;
            const size_t bb = (((size_t)(rb >> 8)) * NC + kc) << 15;
            const uint32_t oa = (uint32_t)(ra & 255) * 128 + h * 64 + q * 16;
            const uint32_t ob = (uint32_t)(rb & 255) * 128 + h * 64 + q * 16;
            cp16(dst0 + ro,                Ab + ba + SWZ128(oa));
            cp16(dst0 + TILE_W * 4 + ro,   Bb + bb + SWZ128(ob));
        }
    };

    for (int mh = 0; mh < 2; ++mh) {
        const int mb0 = m0 + mh * 128;
        for (int np = 0; np < 2; ++np) {
            const int nb0 = n0 + np * 128;

            float acc[2][8][4];
#pragma unroll
            for (int a = 0; a < 2; ++a)
#pragma unroll
                for (int b = 0; b < 8; ++b)
#pragma unroll
                    for (int c = 0; c < 4; ++c) acc[a][b][c] = 0.0f;

            load_chunk(0, 0, mb0, nb0); CP_COMMIT();

            for (int c = 0; c < NC32; ++c) {
                const int st = c & 1;
                if (c + 1 < NC32) { load_chunk(c + 1, st ^ 1, mb0, nb0); CP_COMMIT(); CP_WAIT(1); }
                else              { CP_WAIT(0); }
                __syncthreads();

                const uint32_t* s0 = (const uint32_t*)smem + st * STAGE_W;
#pragma unroll
                for (int ks = 0; ks < 2; ++ks) {
                    uint32_t af[2][4];
#pragma unroll
                    for (int mt = 0; mt < 2; ++mt) {
                        const int rb = wm * 32 + mt * 16;
                        const uint32_t* pa = s0 + (rb + g) * STR + ks * 8 + tg;
                        af[mt][0] = pa[0];           af[mt][2] = pa[4];
                        af[mt][1] = pa[8 * STR];     af[mt][3] = pa[8 * STR + 4];
                    }
#pragma unroll
                    for (int nt = 0; nt < 8; ++nt) {
                        const int nb = wn * 64 + nt * 8;
                        const uint32_t* pb = s0 + TILE_W + (nb + g) * STR + ks * 8 + tg;
                        const uint32_t b0 = pb[0], b1 = pb[4];
#pragma unroll
                        for (int mt = 0; mt < 2; ++mt)
                            mma16816h(acc[mt][nt], af[mt], b0, b1);
                    }
                }
                __syncthreads();
            }

#pragma unroll
            for (int mt = 0; mt < 2; ++mt) {
#pragma unroll
                for (int nt = 0; nt < 8; ++nt) {
                    const int m1 = mb0 + wm * 32 + mt * 16 + g;
                    const int m2 = m1 + 8;
                    const int n  = nb0 + wn * 64 + nt * 8 + tg * 2;
                    const float* a = acc[mt][nt];
                    if (MODE == 4) {
                        const float i1 = 1.0f / rs[zb * SEQ + m1];
                        const float i2 = 1.0f / rs[zb * SEQ + m2];
                        float2 v0; v0.x = a[0] * i1; v0.y = a[1] * i1;
                        float2 v1; v1.x = a[2] * i2; v1.y = a[3] * i2;
                        *(float2*)(Cf + zb * sC + (size_t)m1 * DM + n) = v0;
                        *(float2*)(Cf + zb * sC + (size_t)m2 * DM + n) = v1;
                    } else if (MODE == 0) {
#pragma unroll
                        for (int e = 0; e < 4; ++e) {
                            const int m = (e < 2) ? m1 : m2;
                            const int nn = n + (e & 1);
                            store_blk1(Cb + (size_t)(m >> 11) * 4194304u,
                                       m & 2047, nn, 16, a[e] + bias[nn]);
                        }
                    } else if (MODE == 3) {
                        float e0 = __expf(a[0] * alpha), e1 = __expf(a[1] * alpha);
                        float e2 = __expf(a[2] * alpha), e3 = __expf(a[3] * alpha);
                        atomicAdd(&rs[zb * SEQ + m1], e0 + e1);
                        atomicAdd(&rs[zb * SEQ + m2], e2 + e3);
                        uint8_t* base = Cb + zb * 8388608u;
                        store_blk1(base, m1, n,     32, e0);
                        store_blk1(base, m1, n + 1, 32, e1);
                        store_blk1(base, m2, n,     32, e2);
                        store_blk1(base, m2, n + 1, 32, e3);
                    } else {  // MODE 2
                        uint8_t* base = Cb + zb * 4194304u;
#pragma unroll
                        for (int e = 0; e < 4; ++e) {
                            const int m = (e < 2) ? m1 : m2;
                            const int nn = n + (e & 1);
                            store_blk1(base, m, nn, 32, a[e] + bias[m]);
                        }
                    }
                }
            }
            __syncthreads();
        }
    }
#endif
}

// ---------------------------------------------------------------------------
// f32 -> blocked fp16 (K fixed = 1024; nkc = 16). z selects among 3 tensors.
// ---------------------------------------------------------------------------
__global__ void __launch_bounds__(256) split3_k(
    const float* __restrict__ x0, const float* __restrict__ x1,
    const float* __restrict__ x2,
    uint8_t* __restrict__ d0, uint8_t* __restrict__ d1,
    uint8_t* __restrict__ d2, int nunits)
{
    const int z = blockIdx.z;
    const float* x = (z == 0) ? x0 : (z == 1) ? x1 : x2;
    uint8_t*   dst = (z == 0) ? d0 : (z == 1) ? d1 : d2;
    for (int u = blockIdx.x * 256 + threadIdx.x; u < nunits; u += gridDim.x * 256) {
        const int r = u >> 7;         // row (1024 vals -> 128 units)
        const int j = u & 127;        // unit within row
        const float4 f0 = *(const float4*)(x + ((size_t)r << 10) + (j << 3));
        const float4 f1 = *(const float4*)(x + ((size_t)r << 10) + (j << 3) + 4);
        uint4 hv;
        hv.x = pkh2(__float2half(f0.x), __float2half(f0.y));
        hv.y = pkh2(__float2half(f0.z), __float2half(f0.w));
        hv.z = pkh2(__float2half(f1.x), __float2half(f1.y));
        hv.w = pkh2(__float2half(f1.z), __float2half(f1.w));
        const size_t blk = ((((size_t)(r >> 8)) << 4) + (j >> 3)) << 15;  // nkc=16
        const uint32_t ro = (uint32_t)(r & 255) * 128 + (j & 7) * 16;
        *(uint4*)(dst + blk + SWZ128(ro)) = hv;
    }
}

__global__ void __launch_bounds__(1024) zero_k(float* __restrict__ p, int n)
{
    int i = blockIdx.x * 1024 + threadIdx.x;
    if (i < n) p[i] = 0.0f;
}

// ---------------------------------------------------------------------------
extern "C" void kernel_launch(void* const* d_in, const int* in_sizes, int n_in,
                              void* d_out, int out_size)
{
    (void)in_sizes; (void)n_in; (void)out_size;
    const float* q  = (const float*)d_in[0];
    const float* kx = (const float*)d_in[1];
    const float* vx = (const float*)d_in[2];
    const float* Wq = (const float*)d_in[3];
    const float* bq = (const float*)d_in[4];
    const float* Wk = (const float*)d_in[5];
    const float* bk = (const float*)d_in[6];
    const float* Wv = (const float*)d_in[7];
    const float* bv = (const float*)d_in[8];
    float* out = (float*)d_out;

    uint8_t *Xq, *Xk, *Xv, *Wqb, *Wkb, *Wvb, *Qb, *Kb, *Vt, *Pb;
    float* rs;
    cudaGetSymbolAddress((void**)&Xq,  g_Xq);  cudaGetSymbolAddress((void**)&Xk,  g_Xk);
    cudaGetSymbolAddress((void**)&Xv,  g_Xv);
    cudaGetSymbolAddress((void**)&Wqb, g_Wq);  cudaGetSymbolAddress((void**)&Wkb, g_Wk);
    cudaGetSymbolAddress((void**)&Wvb, g_Wv);
    cudaGetSymbolAddress((void**)&Qb,  g_Qb);  cudaGetSymbolAddress((void**)&Kb,  g_Kb);
    cudaGetSymbolAddress((void**)&Vt,  g_Vt);  cudaGetSymbolAddress((void**)&Pb,  g_Pb);
    cudaGetSymbolAddress((void**)&rs,  g_rs);

    cudaFuncSetAttribute(tc_gemm<0>, cudaFuncAttributeMaxDynamicSharedMemorySize, SMEM_TOTAL);
    cudaFuncSetAttribute(tc_gemm<2>, cudaFuncAttributeMaxDynamicSharedMemorySize, SMEM_TOTAL);
    cudaFuncSetAttribute(tc_gemm<3>, cudaFuncAttributeMaxDynamicSharedMemorySize, SMEM_TOTAL);
    cudaFuncSetAttribute(tc_gemm<4>, cudaFuncAttributeMaxDynamicSharedMemorySize, SMEM_TOTAL);

    // 1. splits (inputs, weights) + zero row sums
    split3_k<<<dim3(2048, 1, 3), 256>>>(q, kx, vx, Xq, Xk, Xv, NTOK * DIN / 8);
    split3_k<<<dim3(512,  1, 3), 256>>>(Wq, Wk, Wv, Wqb, Wkb, Wvb, DM * DIN / 8);
    zero_k<<<(BN * SEQ + 1023) / 1024, 1024>>>(rs, BN * SEQ);

    // 2. Q and K projections in ONE launch (z selects operand set)
    tc_gemm<0><<<dim3(DM / 256, NTOK / 256, 2), 256, SMEM_TOTAL>>>(
        Xq, Wqb, Xk, Wkb, bq, bk, nullptr, Qb, Kb, nullptr,
        DIN, 1.0f, 0, 0, 0);

    // 3. Vt = Wv * Xv^T (+bv)
    tc_gemm<2><<<dim3(SEQ / 256, DM / 256, BN), 256, SMEM_TOTAL>>>(
        Wvb, Xv, nullptr, nullptr, bv, nullptr, nullptr, Vt, nullptr, nullptr,
        DIN, 1.0f, 0, 4194304u, 0);

    // 4. scores + exp + row sums -> fp16 P
    tc_gemm<3><<<dim3(SEQ / 256, SEQ / 256, BN), 256, SMEM_TOTAL>>>(
        Qb, Kb, nullptr, nullptr, nullptr, nullptr, nullptr, Pb, nullptr, rs,
        DM, 0.03125f, 4194304u, 4194304u, 0);

    // 5. O = (P * Vt^T) / rowsum
    tc_gemm<4><<<dim3(DM / 256, SEQ / 256, BN), 256, SMEM_TOTAL>>>(
        Pb, Vt, nullptr, nullptr, nullptr, nullptr, out, nullptr, nullptr, rs,
        SEQ, 1.0f, 8388608u, 4194304u, (size_t)SEQ * DM);
}